// round 1
// baseline (speedup 1.0000x reference)
#include <cuda_runtime.h>
#include <cstdint>

// Problem constants (from reference)
#define BB 512
#define TT 2000
#define DD 3
#define HH 50
// k extent read per step: padded to 52 = 13 * 4 floats (13x LDS.128)
#define KPAD 52

typedef unsigned long long ull;

__device__ __forceinline__ ull packf2(float a, float b) {
    ull r;
    asm("mov.b64 %0, {%1, %2};" : "=l"(r) : "f"(a), "f"(b));
    return r;
}
__device__ __forceinline__ void unpackf2(ull v, float& lo, float& hi) {
    asm("mov.b64 {%0, %1}, %2;" : "=f"(lo), "=f"(hi) : "l"(v));
}
#define FMA2(acc, a, b) \
    asm("fma.rn.f32x2 %0, %1, %2, %0;" : "+l"(acc) : "l"(a), "l"(b))
#define ADD2(dst, a, b) \
    asm("add.rn.f32x2 %0, %1, %2;" : "=l"(dst) : "l"(a), "l"(b))

__global__ __launch_bounds__(128, 1)
void rnn_kernel(const float* __restrict__ x,
                const float* __restrict__ W_ih,
                const float* __restrict__ W_hh,
                const float* __restrict__ b_ih,
                const float* __restrict__ b_hh,
                const float* __restrict__ W_out,
                const float* __restrict__ b_out,
                float* __restrict__ y)
{
    // Per-warp double-buffered hidden state, zero-padded to 64.
    __shared__ __align__(16) float hsh[4][2][64];

    const int warp = threadIdx.x >> 5;
    const int lane = threadIdx.x & 31;
    const int b = blockIdx.x * 4 + warp;   // gridDim.x = 128 -> b in [0,512)

    const int j0 = lane;        // always < 50
    const int j1 = lane + 32;   // valid only if < 50 (lanes 0..17)
    const bool j1v = (j1 < HH);

    // ---- Preload weights into registers ----
    // W_hh rows packed over k: pair p covers k = 2p, 2p+1 ; 26 pairs covers k in [0,52)
    ull w0[26], w1[26];
#pragma unroll
    for (int p = 0; p < 26; p++) {
        const int k0 = 2 * p, k1 = 2 * p + 1;
        float a0 = (k0 < HH) ? W_hh[j0 * HH + k0] : 0.f;
        float a1 = (k1 < HH) ? W_hh[j0 * HH + k1] : 0.f;
        float c0 = (j1v && k0 < HH) ? W_hh[j1 * HH + k0] : 0.f;
        float c1 = (j1v && k1 < HH) ? W_hh[j1 * HH + k1] : 0.f;
        w0[p] = packf2(a0, a1);
        w1[p] = packf2(c0, c1);
    }
    // input projection weights + fused bias (b_ih + b_hh)
    const float wi0a = W_ih[j0 * DD + 0], wi0b = W_ih[j0 * DD + 1], wi0c = W_ih[j0 * DD + 2];
    const float bias0 = b_ih[j0] + b_hh[j0];
    const float wi1a = j1v ? W_ih[j1 * DD + 0] : 0.f;
    const float wi1b = j1v ? W_ih[j1 * DD + 1] : 0.f;
    const float wi1c = j1v ? W_ih[j1 * DD + 2] : 0.f;
    const float bias1 = j1v ? (b_ih[j1] + b_hh[j1]) : 0.f;
    // output projection weights for this lane's two j's
    float wo0[3], wo1[3];
#pragma unroll
    for (int d = 0; d < 3; d++) {
        wo0[d] = W_out[d * HH + j0];
        wo1[d] = j1v ? W_out[d * HH + j1] : 0.f;
    }
    const float bo = (lane < 3) ? b_out[lane] : 0.f;

    // ---- init h = 0 (both buffers) ----
    hsh[warp][0][lane] = 0.f;  hsh[warp][0][lane + 32] = 0.f;
    hsh[warp][1][lane] = 0.f;  hsh[warp][1][lane + 32] = 0.f;
    __syncwarp();

    const float* __restrict__ xb = x + (size_t)b * TT * DD;
    float* __restrict__ yb = y + (size_t)b * TT * DD;

    int buf = 0;
#pragma unroll 1
    for (int t = 0; t < TT; t++) {
        // input projection (broadcast loads, L1 hits)
        const float x0 = __ldg(xb + 3 * t + 0);
        const float x1 = __ldg(xb + 3 * t + 1);
        const float x2 = __ldg(xb + 3 * t + 2);
        const float xh0 = fmaf(x2, wi0c, fmaf(x1, wi0b, fmaf(x0, wi0a, bias0)));
        const float xh1 = fmaf(x2, wi1c, fmaf(x1, wi1b, fmaf(x0, wi1a, bias1)));

        // recurrence dot: 13 x LDS.128 (broadcast) + 52 x fma.rn.f32x2
        ull acc00 = 0ull, acc01 = 0ull, acc10 = 0ull, acc11 = 0ull;
        const ulonglong2* __restrict__ hb =
            reinterpret_cast<const ulonglong2*>(&hsh[warp][buf][0]);
#pragma unroll
        for (int p = 0; p < 13; p++) {
            const ulonglong2 hv = hb[p];            // h[4p..4p+3]
            FMA2(acc00, hv.x, w0[2 * p]);
            FMA2(acc01, hv.y, w0[2 * p + 1]);
            FMA2(acc10, hv.x, w1[2 * p]);
            FMA2(acc11, hv.y, w1[2 * p + 1]);
        }
        ull s0, s1;
        ADD2(s0, acc00, acc01);
        ADD2(s1, acc10, acc11);
        float l0, h0hi, l1, h1hi;
        unpackf2(s0, l0, h0hi);
        unpackf2(s1, l1, h1hi);
        const float h0 = fmaxf(xh0 + l0 + h0hi, 0.f);
        const float h1 = fmaxf(xh1 + l1 + h1hi, 0.f);

        // write new hidden state into other buffer
        hsh[warp][buf ^ 1][lane]      = h0;
        hsh[warp][buf ^ 1][lane + 32] = h1;   // zero for padded j's by construction
        __syncwarp();
        buf ^= 1;

        // fused output projection: y[b,t,d] = sum_j h[j]*W_out[d][j] + b_out[d]
        float p0 = fmaf(h0, wo0[0], h1 * wo1[0]);
        float p1 = fmaf(h0, wo0[1], h1 * wo1[1]);
        float p2 = fmaf(h0, wo0[2], h1 * wo1[2]);
#pragma unroll
        for (int off = 16; off > 0; off >>= 1) {
            p0 += __shfl_xor_sync(0xffffffffu, p0, off);
            p1 += __shfl_xor_sync(0xffffffffu, p1, off);
            p2 += __shfl_xor_sync(0xffffffffu, p2, off);
        }
        if (lane < 3) {
            const float v = (lane == 0) ? p0 : (lane == 1) ? p1 : p2;
            yb[3 * t + lane] = v + bo;
        }
    }
}

extern "C" void kernel_launch(void* const* d_in, const int* in_sizes, int n_in,
                              void* d_out, int out_size) {
    const float* x     = (const float*)d_in[0];
    const float* W_ih  = (const float*)d_in[1];
    const float* W_hh  = (const float*)d_in[2];
    const float* b_ih  = (const float*)d_in[3];
    const float* b_hh  = (const float*)d_in[4];
    const float* W_out = (const float*)d_in[5];
    const float* b_out = (const float*)d_in[6];
    float* y = (float*)d_out;

    rnn_kernel<<<BB / 4, 128>>>(x, W_ih, W_hh, b_ih, b_hh, W_out, b_out, y);
}

// round 2
// speedup vs baseline: 1.7651x; 1.7651x over previous
#include <cuda_runtime.h>
#include <cstdint>

#define BB 512
#define TT 2000
#define DD 3
#define HH 50

typedef unsigned long long ull;

__device__ __forceinline__ ull packf2(float a, float b) {
    ull r;
    asm("mov.b64 %0, {%1, %2};" : "=l"(r) : "f"(a), "f"(b));
    return r;
}
__device__ __forceinline__ void unpackf2(ull v, float& lo, float& hi) {
    asm("mov.b64 {%0, %1}, %2;" : "=f"(lo), "=f"(hi) : "l"(v));
}
#define FMA2(acc, a, b) \
    asm("fma.rn.f32x2 %0, %1, %2, %0;" : "+l"(acc) : "l"(a), "l"(b))
#define ADD2(dst, a, b) \
    asm("add.rn.f32x2 %0, %1, %2;" : "=l"(dst) : "l"(a), "l"(b))

// hist row stride in floats: 68 = 17 * 4 (keeps every row 16B aligned)
#define HSTRIDE 68

__global__ __launch_bounds__(128, 1)
void rnn_kernel(const float* __restrict__ x,
                const float* __restrict__ W_ih,
                const float* __restrict__ W_hh,
                const float* __restrict__ b_ih,
                const float* __restrict__ b_hh,
                const float* __restrict__ W_out,
                const float* __restrict__ b_out,
                float* __restrict__ y)
{
    // 32-step hidden-state history ring per warp (also the recurrence buffer)
    __shared__ __align__(16) float hist[4][32][HSTRIDE];   // 34,816 B
    __shared__ ull  wosh[3][26];                           // packed W_out pairs
    __shared__ float bosh[3];

    const int warp = threadIdx.x >> 5;
    const int lane = threadIdx.x & 31;
    const int tid  = threadIdx.x;
    const int b = blockIdx.x * 4 + warp;

    // ---- build packed W_out in shared (block-common) ----
    if (tid < 78) {
        const int d = tid / 26, q = tid % 26;
        const int k0 = 2 * q, k1 = 2 * q + 1;
        const float a = (k0 < HH) ? W_out[d * HH + k0] : 0.f;
        const float c = (k1 < HH) ? W_out[d * HH + k1] : 0.f;
        wosh[d][q] = packf2(a, c);
    }
    if (tid < 3) bosh[tid] = b_out[tid];

    // h_{-1} = 0 lives in ring row 31
    hist[warp][31][lane] = 0.f;
    hist[warp][31][lane + 32] = 0.f;
    if (lane < 4) hist[warp][31][lane + 64] = 0.f;
    __syncthreads();

    const int j0 = lane;
    const int j1 = lane + 32;
    const bool j1v = (j1 < HH);

    // ---- W_hh packed into registers: w[2p] covers k=(4p,4p+1), w[2p+1] k=(4p+2,4p+3)
    ull w0[26], w1[26];
#pragma unroll
    for (int p = 0; p < 26; p++) {
        const int k0 = 2 * p, k1 = 2 * p + 1;
        float a0 = (k0 < HH) ? W_hh[j0 * HH + k0] : 0.f;
        float a1 = (k1 < HH) ? W_hh[j0 * HH + k1] : 0.f;
        float c0 = (j1v && k0 < HH) ? W_hh[j1 * HH + k0] : 0.f;
        float c1 = (j1v && k1 < HH) ? W_hh[j1 * HH + k1] : 0.f;
        w0[p] = packf2(a0, a1);
        w1[p] = packf2(c0, c1);
    }
    const float wi0a = W_ih[j0 * DD + 0], wi0b = W_ih[j0 * DD + 1], wi0c = W_ih[j0 * DD + 2];
    const float bias0 = b_ih[j0] + b_hh[j0];
    const float wi1a = j1v ? W_ih[j1 * DD + 0] : 0.f;
    const float wi1b = j1v ? W_ih[j1 * DD + 1] : 0.f;
    const float wi1c = j1v ? W_ih[j1 * DD + 2] : 0.f;
    const float bias1 = j1v ? (b_ih[j1] + b_hh[j1]) : 0.f;

    const float* __restrict__ xb = x + (size_t)b * TT * DD;
    float* __restrict__ yb = y + (size_t)b * TT * DD;

    // prefetch x for t=0
    float nx0 = __ldg(xb + 0), nx1 = __ldg(xb + 1), nx2 = __ldg(xb + 2);

    for (int base = 0; base < TT; base += 32) {
        const int cnt = min(32, TT - base);

#pragma unroll 1
        for (int s = 0; s < cnt; s++) {
            const int t = base + s;
            const float x0 = nx0, x1 = nx1, x2 = nx2;
            const int tn = (t + 1 < TT) ? t + 1 : t;
            nx0 = __ldg(xb + 3 * tn + 0);
            nx1 = __ldg(xb + 3 * tn + 1);
            nx2 = __ldg(xb + 3 * tn + 2);

            const float xh0 = fmaf(x2, wi0c, fmaf(x1, wi0b, fmaf(x0, wi0a, bias0)));
            const float xh1 = fmaf(x2, wi1c, fmaf(x1, wi1b, fmaf(x0, wi1a, bias1)));

            // broadcast read of h_{t-1}: 13x LDS.128, conflict-free
            const ulonglong2* __restrict__ hb =
                reinterpret_cast<const ulonglong2*>(&hist[warp][(t + 31) & 31][0]);

            // 8 accumulator chains (depth 7) over 52 packed FMAs
            ull a00 = 0ull, a01 = 0ull, a02 = 0ull, a03 = 0ull;
            ull a10 = 0ull, a11 = 0ull, a12 = 0ull, a13 = 0ull;
#pragma unroll
            for (int p = 0; p < 13; p++) {
                const ulonglong2 hv = hb[p];
                if (p & 1) {
                    FMA2(a02, hv.x, w0[2 * p]);
                    FMA2(a03, hv.y, w0[2 * p + 1]);
                    FMA2(a12, hv.x, w1[2 * p]);
                    FMA2(a13, hv.y, w1[2 * p + 1]);
                } else {
                    FMA2(a00, hv.x, w0[2 * p]);
                    FMA2(a01, hv.y, w0[2 * p + 1]);
                    FMA2(a10, hv.x, w1[2 * p]);
                    FMA2(a11, hv.y, w1[2 * p + 1]);
                }
            }
            ull s0a, s0b, s1a, s1b, s0, s1;
            ADD2(s0a, a00, a01); ADD2(s0b, a02, a03); ADD2(s0, s0a, s0b);
            ADD2(s1a, a10, a11); ADD2(s1b, a12, a13); ADD2(s1, s1a, s1b);
            float l0, u0, l1, u1;
            unpackf2(s0, l0, u0);
            unpackf2(s1, l1, u1);
            const float h0 = fmaxf(xh0 + (l0 + u0), 0.f);
            const float h1 = fmaxf(xh1 + (l1 + u1), 0.f);   // exact 0 for padded j1

            float* hw = &hist[warp][t & 31][0];
            hw[lane] = h0;
            hw[lane + 32] = h1;
            __syncwarp();
        }

        // ---- chunk projection: lane s' owns timestep base+s' ----
        {
            const ulonglong2* __restrict__ hr =
                reinterpret_cast<const ulonglong2*>(&hist[warp][lane][0]);
            ull a0x = 0ull, a0y = 0ull, a1x = 0ull, a1y = 0ull, a2x = 0ull, a2y = 0ull;
#pragma unroll
            for (int p = 0; p < 13; p++) {
                const ulonglong2 hv = hr[p];
                FMA2(a0x, hv.x, wosh[0][2 * p]);
                FMA2(a0y, hv.y, wosh[0][2 * p + 1]);
                FMA2(a1x, hv.x, wosh[1][2 * p]);
                FMA2(a1y, hv.y, wosh[1][2 * p + 1]);
                FMA2(a2x, hv.x, wosh[2][2 * p]);
                FMA2(a2y, hv.y, wosh[2][2 * p + 1]);
            }
            ull s0, s1, s2;
            ADD2(s0, a0x, a0y);
            ADD2(s1, a1x, a1y);
            ADD2(s2, a2x, a2y);
            float p0l, p0h, p1l, p1h, p2l, p2h;
            unpackf2(s0, p0l, p0h);
            unpackf2(s1, p1l, p1h);
            unpackf2(s2, p2l, p2h);
            if (lane < cnt) {
                float* yo = yb + (size_t)(base + lane) * 3;
                yo[0] = p0l + p0h + bosh[0];
                yo[1] = p1l + p1h + bosh[1];
                yo[2] = p2l + p2h + bosh[2];
            }
            __syncwarp();   // projection reads must finish before next chunk overwrites ring
        }
    }
}

extern "C" void kernel_launch(void* const* d_in, const int* in_sizes, int n_in,
                              void* d_out, int out_size) {
    const float* x     = (const float*)d_in[0];
    const float* W_ih  = (const float*)d_in[1];
    const float* W_hh  = (const float*)d_in[2];
    const float* b_ih  = (const float*)d_in[3];
    const float* b_hh  = (const float*)d_in[4];
    const float* W_out = (const float*)d_in[5];
    const float* b_out = (const float*)d_in[6];
    float* y = (float*)d_out;

    rnn_kernel<<<BB / 4, 128>>>(x, W_ih, W_hh, b_ih, b_hh, W_out, b_out, y);
}